// round 3
// baseline (speedup 1.0000x reference)
#include <cuda_runtime.h>
#include <cstdint>

// Shape: x [B=4, S=2048, D=1024] fp32; Wq/Wk/Wv [D, D] fp32 (y = x @ W^T)
#define BATCH 4
#define SEQ   2048
#define DM    1024
#define MTOT  (BATCH * SEQ)   // 8192

__device__ float g_Q[BATCH * SEQ * DM];
__device__ float g_K[BATCH * SEQ * DM];
__device__ float g_V[BATCH * SEQ * DM];
__device__ float g_P[BATCH * SEQ * SEQ];

// ---------------------------------------------------------------------------
// TF32 mma.sync GEMM, fragment-major smem + double buffering.
// Block tile 128x128, BK=16, 256 threads = 8 warps (2x4), warp tile 64x32.
// Smem layouts (per buffer):
//   Af[16][128]: slot = ks*8 + im (im = m16 block 0..7), within slot:
//                lane*4 + j,  j = mhi + 2*khi  -> lane reads LDS.128
//   Bf[32][64] : slot = ks*16 + inb (inb = n8 block 0..15), within slot:
//                lane*2 + khi -> lane reads LDS.64
// ---------------------------------------------------------------------------
#define BM 128
#define BN 128
#define BK 16

__device__ __forceinline__ uint32_t f2tf32(float f) {
    uint32_t o;
    asm("cvt.rna.tf32.f32 %0, %1;" : "=r"(o) : "f"(f));
    return o;
}

__device__ __forceinline__ void mma_tf32(
    float c[4], uint32_t a0, uint32_t a1, uint32_t a2, uint32_t a3,
    uint32_t b0, uint32_t b1)
{
    asm volatile(
        "mma.sync.aligned.m16n8k8.row.col.f32.tf32.tf32.f32 "
        "{%0,%1,%2,%3}, {%4,%5,%6,%7}, {%8,%9}, {%0,%1,%2,%3};"
        : "+f"(c[0]), "+f"(c[1]), "+f"(c[2]), "+f"(c[3])
        : "r"(a0), "r"(a1), "r"(a2), "r"(a3), "r"(b0), "r"(b1));
}

// B_NK = true : C[m][n] = sum_k A[m][k] * B[n][k]   (B row-major [N,K])
// B_NK = false: C[m][n] = sum_k A[m][k] * B[k][n]   (B row-major [K,N])
template <bool B_NK>
__device__ __forceinline__ void gemm_tf32_body(
    const float* __restrict__ A, const float* __restrict__ Bm,
    float* __restrict__ C, int N, int K)
{
    __shared__ uint32_t Af[2][16][128];
    __shared__ uint32_t Bf[2][32][64];

    const int t    = threadIdx.x;
    const int lane = t & 31;
    const int warp = t >> 5;
    const int m0   = blockIdx.y * BM;
    const int n0   = blockIdx.x * BN;

    const int wm = (warp >> 2) * 64;   // warp row offset (0/64)
    const int wn = (warp & 3) * 32;    // warp col offset (0/32/64/96)
    const int fr = lane >> 2;
    const int fc = lane & 3;

    float acc[4][4][4];
#pragma unroll
    for (int i = 0; i < 4; i++)
#pragma unroll
        for (int j = 0; j < 4; j++)
#pragma unroll
            for (int r = 0; r < 4; r++) acc[i][j][r] = 0.f;

    // ---- loader index precompute (2 float4 per thread per array) ----
    // A (and B_NK): idx -> row = idx>>2 (0..127), kq = (idx&3)*4
    // B_KN        : idx -> k = idx>>5 (0..15),   n4 = (idx&31)*4
    int a_row[2], a_kq[2], a_slot[2], a_j[2];
    int b_slot[2], b_off[2];  // base offset within slot row for q=0
    int b_stride;             // offset step per q
#pragma unroll
    for (int it = 0; it < 2; it++) {
        int idx = t + it * 256;
        int row = idx >> 2, kq = (idx & 3) * 4;
        a_row[it]  = row; a_kq[it] = kq;
        int im = row >> 4, frA = row & 7, mhi = (row >> 3) & 1;
        int ks = kq >> 3, khi = (kq >> 2) & 1;
        a_slot[it] = ks * 8 + im;
        a_j[it]    = mhi + 2 * khi;
        // A write q: Af[buf][a_slot][(frA*4+q)*4 + a_j], base = frA*16 + a_j
        a_row[it]  = row;           // gmem row
        a_slot[it] = a_slot[it];
        a_j[it]    = frA * 16 + a_j[it];  // fold frA in; q step = 4
        if (B_NK) {
            int inb = row >> 3, frB = row & 7;
            b_slot[it] = ks * 16 + inb;
            b_off[it]  = frB * 8 + khi;   // (frB*4+q)*2 + khi ; q step = 2
        } else {
            int k = idx >> 5, n4 = (idx & 31) * 4;
            int ksB = k >> 3, kk = k & 7, fcB = kk & 3, khiB = kk >> 2;
            int inb = n4 >> 3, frb = n4 & 7;  // 0 or 4
            b_slot[it] = ksB * 16 + inb;
            b_off[it]  = (frb * 4 + fcB) * 2 + khiB;  // q step = 8
        }
    }
    b_stride = B_NK ? 2 : 8;

    float4 pa[2], pb[2];

    // ---- prefetch tile 0 ----
#pragma unroll
    for (int it = 0; it < 2; it++) {
        pa[it] = *(const float4*)(A + (long)(m0 + a_row[it]) * K + a_kq[it]);
        if (B_NK) {
            int idx = t + it * 256;
            int row = idx >> 2, kq = (idx & 3) * 4;
            pb[it] = *(const float4*)(Bm + (long)(n0 + row) * K + kq);
        } else {
            int idx = t + it * 256;
            int k = idx >> 5, n4 = (idx & 31) * 4;
            pb[it] = *(const float4*)(Bm + (long)k * N + n0 + n4);
        }
    }

    // store tile 0 -> buf 0
#pragma unroll
    for (int it = 0; it < 2; it++) {
        uint32_t* ap = &Af[0][a_slot[it]][a_j[it]];
        ap[0]  = f2tf32(pa[it].x);
        ap[4]  = f2tf32(pa[it].y);
        ap[8]  = f2tf32(pa[it].z);
        ap[12] = f2tf32(pa[it].w);
        uint32_t* bp = &Bf[0][b_slot[it]][b_off[it]];
        bp[0]            = f2tf32(pb[it].x);
        bp[b_stride]     = f2tf32(pb[it].y);
        bp[2 * b_stride] = f2tf32(pb[it].z);
        bp[3 * b_stride] = f2tf32(pb[it].w);
    }
    __syncthreads();

    const int nTiles = K / BK;
    for (int ti = 0; ti < nTiles; ti++) {
        const int buf = ti & 1;
        const bool more = (ti + 1) < nTiles;

        // prefetch next tile (LDG early, consumed after compute)
        if (more) {
            const int kn = (ti + 1) * BK;
#pragma unroll
            for (int it = 0; it < 2; it++) {
                pa[it] = *(const float4*)(A + (long)(m0 + a_row[it]) * K + kn + a_kq[it]);
                if (B_NK) {
                    int idx = t + it * 256;
                    int row = idx >> 2, kq = (idx & 3) * 4;
                    pb[it] = *(const float4*)(Bm + (long)(n0 + row) * K + kn + kq);
                } else {
                    int idx = t + it * 256;
                    int k = idx >> 5, n4 = (idx & 31) * 4;
                    pb[it] = *(const float4*)(Bm + (long)(kn + k) * N + n0 + n4);
                }
            }
        }

        // compute 2 k-steps from buf
#pragma unroll
        for (int ks = 0; ks < 2; ks++) {
            uint32_t af[4][4], bf[4][2];
#pragma unroll
            for (int im = 0; im < 4; im++) {
                uint4 v = *(const uint4*)&Af[buf][ks * 8 + (wm >> 4) + im][lane * 4];
                af[im][0] = v.x; af[im][1] = v.y; af[im][2] = v.z; af[im][3] = v.w;
            }
#pragma unroll
            for (int in = 0; in < 4; in++) {
                uint2 v = *(const uint2*)&Bf[buf][ks * 16 + (wn >> 3) + in][lane * 2];
                bf[in][0] = v.x; bf[in][1] = v.y;
            }
#pragma unroll
            for (int im = 0; im < 4; im++)
#pragma unroll
                for (int in = 0; in < 4; in++)
                    mma_tf32(acc[im][in], af[im][0], af[im][1], af[im][2], af[im][3],
                             bf[in][0], bf[in][1]);
        }

        // store prefetched tile into other buffer, one sync
        if (more) {
            const int nb = buf ^ 1;
#pragma unroll
            for (int it = 0; it < 2; it++) {
                uint32_t* ap = &Af[nb][a_slot[it]][a_j[it]];
                ap[0]  = f2tf32(pa[it].x);
                ap[4]  = f2tf32(pa[it].y);
                ap[8]  = f2tf32(pa[it].z);
                ap[12] = f2tf32(pa[it].w);
                uint32_t* bp = &Bf[nb][b_slot[it]][b_off[it]];
                bp[0]            = f2tf32(pb[it].x);
                bp[b_stride]     = f2tf32(pb[it].y);
                bp[2 * b_stride] = f2tf32(pb[it].z);
                bp[3 * b_stride] = f2tf32(pb[it].w);
            }
            __syncthreads();
        }
    }

    // epilogue
#pragma unroll
    for (int im = 0; im < 4; im++) {
#pragma unroll
        for (int in = 0; in < 4; in++) {
            long row = m0 + wm + im * 16 + fr;
            long col = n0 + wn + in * 8 + 2 * fc;
            *(float2*)(C + row * N + col)       = make_float2(acc[im][in][0], acc[im][in][1]);
            *(float2*)(C + (row + 8) * N + col) = make_float2(acc[im][in][2], acc[im][in][3]);
        }
    }
}

// ---------------------------------------------------------------------------
__global__ __launch_bounds__(256) void qkv_kernel(
    const float* __restrict__ x,
    const float* __restrict__ Wq,
    const float* __restrict__ Wk,
    const float* __restrict__ Wv)
{
    const float* W = (blockIdx.z == 0) ? Wq : (blockIdx.z == 1) ? Wk : Wv;
    float* C       = (blockIdx.z == 0) ? g_Q : (blockIdx.z == 1) ? g_K : g_V;
    gemm_tf32_body<true>(x, W, C, DM, DM);
}

__global__ __launch_bounds__(256) void scores_kernel()
{
    const long b = blockIdx.z;
    gemm_tf32_body<true>(g_Q + b * (long)SEQ * DM,
                         g_K + b * (long)SEQ * DM,
                         g_P + b * (long)SEQ * SEQ, SEQ, DM);
}

__global__ __launch_bounds__(256) void softmax_kernel()
{
    const long row = blockIdx.x;
    float* p = g_P + row * (long)SEQ;
    const int t = threadIdx.x;
    const float scale = 0.03125f;  // 1/sqrt(1024)

    float4 v0 = ((const float4*)p)[t];
    float4 v1 = ((const float4*)p)[t + 256];

    float m = fmaxf(fmaxf(fmaxf(v0.x, v0.y), fmaxf(v0.z, v0.w)),
                    fmaxf(fmaxf(v1.x, v1.y), fmaxf(v1.z, v1.w)));
    m *= scale;

    __shared__ float red[256];
    red[t] = m; __syncthreads();
#pragma unroll
    for (int s = 128; s > 0; s >>= 1) {
        if (t < s) red[t] = fmaxf(red[t], red[t + s]);
        __syncthreads();
    }
    const float rowmax = red[0];
    __syncthreads();

    float e[8];
    e[0] = __expf(fmaf(v0.x, scale, -rowmax));
    e[1] = __expf(fmaf(v0.y, scale, -rowmax));
    e[2] = __expf(fmaf(v0.z, scale, -rowmax));
    e[3] = __expf(fmaf(v0.w, scale, -rowmax));
    e[4] = __expf(fmaf(v1.x, scale, -rowmax));
    e[5] = __expf(fmaf(v1.y, scale, -rowmax));
    e[6] = __expf(fmaf(v1.z, scale, -rowmax));
    e[7] = __expf(fmaf(v1.w, scale, -rowmax));

    float s8 = e[0]+e[1]+e[2]+e[3]+e[4]+e[5]+e[6]+e[7];
    red[t] = s8; __syncthreads();
#pragma unroll
    for (int s = 128; s > 0; s >>= 1) {
        if (t < s) red[t] += red[t + s];
        __syncthreads();
    }
    const float inv = 1.0f / red[0];

    ((float4*)p)[t]       = make_float4(e[0]*inv, e[1]*inv, e[2]*inv, e[3]*inv);
    ((float4*)p)[t + 256] = make_float4(e[4]*inv, e[5]*inv, e[6]*inv, e[7]*inv);
}

__global__ __launch_bounds__(256) void out_kernel(float* __restrict__ out)
{
    const long b = blockIdx.z;
    gemm_tf32_body<false>(g_P + b * (long)SEQ * SEQ,
                          g_V + b * (long)SEQ * DM,
                          out + b * (long)SEQ * DM, DM, SEQ);
}

// ---------------------------------------------------------------------------
extern "C" void kernel_launch(void* const* d_in, const int* in_sizes, int n_in,
                              void* d_out, int out_size)
{
    const float* x  = (const float*)d_in[0];
    const float* Wq = (const float*)d_in[1];
    const float* Wk = (const float*)d_in[2];
    const float* Wv = (const float*)d_in[3];
    float* out = (float*)d_out;

    dim3 blk(256);
    qkv_kernel   <<<dim3(DM / BN,  MTOT / BM, 3),     blk>>>(x, Wq, Wk, Wv);
    scores_kernel<<<dim3(SEQ / BN, SEQ / BM,  BATCH), blk>>>();
    softmax_kernel<<<BATCH * SEQ, 256>>>();
    out_kernel   <<<dim3(DM / BN,  SEQ / BM,  BATCH), blk>>>(out);
}

// round 4
// speedup vs baseline: 2.0378x; 2.0378x over previous
#include <cuda_runtime.h>
#include <cstdint>

// Shape: x [B=4, S=2048, D=1024] fp32; Wq/Wk/Wv [D, D] fp32 (y = x @ W^T)
#define BATCH 4
#define SEQ   2048
#define DM    1024
#define MTOT  (BATCH * SEQ)   // 8192

__device__ float g_Q[BATCH * SEQ * DM];
__device__ float g_K[BATCH * SEQ * DM];
__device__ float g_V[BATCH * SEQ * DM];
__device__ float g_P[BATCH * SEQ * SEQ];

// ---------------------------------------------------------------------------
// TF32 mma.sync GEMM + ldmatrix.
// Block tile 128x128, BK=16, 256 threads = 8 warps (2x4), warp tile 64x32.
// A smem:  As[128][ASTR=20]  (k-contiguous rows; pad 4 -> LDSM conflict-free)
// B smem:  B_NK: same layout as A (rows = n).
//          B_KN: Bs[16][136] (n-contiguous rows; scalar LDS, conflict-free).
// ---------------------------------------------------------------------------
#define BM 128
#define BN 128
#define BK 16
#define ASTR 20
#define KNSTR 136

__device__ __forceinline__ uint32_t f2tf32(float f) {
    uint32_t o;
    asm("cvt.rna.tf32.f32 %0, %1;" : "=r"(o) : "f"(f));
    return o;
}

__device__ __forceinline__ void mma_tf32(
    float c[4], uint32_t a0, uint32_t a1, uint32_t a2, uint32_t a3,
    uint32_t b0, uint32_t b1)
{
    asm volatile(
        "mma.sync.aligned.m16n8k8.row.col.f32.tf32.tf32.f32 "
        "{%0,%1,%2,%3}, {%4,%5,%6,%7}, {%8,%9}, {%0,%1,%2,%3};"
        : "+f"(c[0]), "+f"(c[1]), "+f"(c[2]), "+f"(c[3])
        : "r"(a0), "r"(a1), "r"(a2), "r"(a3), "r"(b0), "r"(b1));
}

__device__ __forceinline__ void ldsm_x4(
    uint32_t& r0, uint32_t& r1, uint32_t& r2, uint32_t& r3, uint32_t addr)
{
    asm volatile("ldmatrix.sync.aligned.m8n8.x4.shared.b16 {%0,%1,%2,%3}, [%4];"
                 : "=r"(r0), "=r"(r1), "=r"(r2), "=r"(r3) : "r"(addr));
}

// B_NK = true : C[m][n] = sum_k A[m][k] * B[n][k]   (B row-major [N,K])
// B_NK = false: C[m][n] = sum_k A[m][k] * B[k][n]   (B row-major [K,N])
template <bool B_NK>
__device__ __forceinline__ void gemm_tf32_body(
    const float* __restrict__ A, const float* __restrict__ Bm,
    float* __restrict__ C, int N, int K)
{
    __shared__ uint32_t As[2][128 * ASTR];
    __shared__ uint32_t Bs[2][B_NK ? (128 * ASTR) : (BK * KNSTR)];

    const int t    = threadIdx.x;
    const int lane = t & 31;
    const int warp = t >> 5;
    const int m0   = blockIdx.y * BM;
    const int n0   = blockIdx.x * BN;

    const int wm = (warp >> 2) * 64;   // warp row offset (0/64)
    const int wn = (warp & 3) * 32;    // warp col offset (0/32/64/96)
    const int fr = lane >> 2;
    const int fc = lane & 3;

    const uint32_t asBase = (uint32_t)__cvta_generic_to_shared(&As[0][0]);
    const uint32_t bsBase = (uint32_t)__cvta_generic_to_shared(&Bs[0][0]);

    // ldmatrix per-lane address pieces.
    // A x4 (for af[im]): matrices {(r,k0),(r+8,k0),(r,k4),(r+8,k4)}
    //   j = lane>>3 : row += (j&1)*8, k += (j>>1)*4
    const int a_lm_row = wm + ((lane >> 3) & 1) * 8 + (lane & 7);
    const int a_lm_k   = ((lane >> 4) & 1) * 4;
    // B x4 (for bf[2p],bf[2p+1]): matrices {(n,k0),(n,k4),(n+8,k0),(n+8,k4)}
    //   j = lane>>3 : k += (j&1)*4, n += (j>>1)*8
    const int b_lm_n = wn + ((lane >> 4) & 1) * 8 + (lane & 7);
    const int b_lm_k = ((lane >> 3) & 1) * 4;

    float acc[4][4][4];
#pragma unroll
    for (int i = 0; i < 4; i++)
#pragma unroll
        for (int j = 0; j < 4; j++)
#pragma unroll
            for (int r = 0; r < 4; r++) acc[i][j][r] = 0.f;

    // loader mapping (2 float4 per thread per array)
    // rows-major arrays: row = idx>>2 (0..127), kq = (idx&3)*4
    // B_KN:              k   = idx>>5 (0..15),  n4 = (idx&31)*4
    float4 pa[2], pb[2];

#pragma unroll
    for (int it = 0; it < 2; it++) {
        int idx = t + it * 256;
        int row = idx >> 2, kq = (idx & 3) * 4;
        pa[it] = *(const float4*)(A + (long)(m0 + row) * K + kq);
        if (B_NK) {
            pb[it] = *(const float4*)(Bm + (long)(n0 + row) * K + kq);
        } else {
            int k = idx >> 5, n4 = (idx & 31) * 4;
            pb[it] = *(const float4*)(Bm + (long)k * N + n0 + n4);
        }
    }

    auto store_tile = [&](int buf) {
#pragma unroll
        for (int it = 0; it < 2; it++) {
            int idx = t + it * 256;
            int row = idx >> 2, kq = (idx & 3) * 4;
            uint4 av = make_uint4(f2tf32(pa[it].x), f2tf32(pa[it].y),
                                  f2tf32(pa[it].z), f2tf32(pa[it].w));
            *(uint4*)&As[buf][row * ASTR + kq] = av;
            uint4 bv = make_uint4(f2tf32(pb[it].x), f2tf32(pb[it].y),
                                  f2tf32(pb[it].z), f2tf32(pb[it].w));
            if (B_NK) {
                *(uint4*)&Bs[buf][row * ASTR + kq] = bv;
            } else {
                int k = idx >> 5, n4 = (idx & 31) * 4;
                *(uint4*)&Bs[buf][k * KNSTR + n4] = bv;
            }
        }
    };

    store_tile(0);
    __syncthreads();

    const int nTiles = K / BK;
    for (int ti = 0; ti < nTiles; ti++) {
        const int buf = ti & 1;
        const bool more = (ti + 1) < nTiles;

        if (more) {
            const int kn = (ti + 1) * BK;
#pragma unroll
            for (int it = 0; it < 2; it++) {
                int idx = t + it * 256;
                int row = idx >> 2, kq = (idx & 3) * 4;
                pa[it] = *(const float4*)(A + (long)(m0 + row) * K + kn + kq);
                if (B_NK) {
                    pb[it] = *(const float4*)(Bm + (long)(n0 + row) * K + kn + kq);
                } else {
                    int k = idx >> 5, n4 = (idx & 31) * 4;
                    pb[it] = *(const float4*)(Bm + (long)(kn + k) * N + n0 + n4);
                }
            }
        }

        const uint32_t aBufB = asBase + (uint32_t)(buf * 128 * ASTR) * 4u;
        const uint32_t bBufB = bsBase +
            (uint32_t)(buf * (B_NK ? 128 * ASTR : BK * KNSTR)) * 4u;

#pragma unroll
        for (int ks = 0; ks < 2; ks++) {
            const int kb = ks * 8;
            uint32_t af[4][4], bf[4][2];
#pragma unroll
            for (int im = 0; im < 4; im++) {
                uint32_t addr = aBufB +
                    (uint32_t)((a_lm_row + im * 16) * ASTR + kb + a_lm_k) * 4u;
                ldsm_x4(af[im][0], af[im][1], af[im][2], af[im][3], addr);
            }
            if (B_NK) {
#pragma unroll
                for (int p = 0; p < 2; p++) {
                    uint32_t addr = bBufB +
                        (uint32_t)((b_lm_n + p * 16) * ASTR + kb + b_lm_k) * 4u;
                    ldsm_x4(bf[2 * p][0], bf[2 * p][1],
                            bf[2 * p + 1][0], bf[2 * p + 1][1], addr);
                }
            } else {
#pragma unroll
                for (int in = 0; in < 4; in++) {
                    bf[in][0] = Bs[buf][(kb + fc) * KNSTR + wn + in * 8 + fr];
                    bf[in][1] = Bs[buf][(kb + fc + 4) * KNSTR + wn + in * 8 + fr];
                }
            }
#pragma unroll
            for (int im = 0; im < 4; im++)
#pragma unroll
                for (int in = 0; in < 4; in++)
                    mma_tf32(acc[im][in], af[im][0], af[im][1], af[im][2], af[im][3],
                             bf[in][0], bf[in][1]);
        }

        if (more) {
            store_tile(buf ^ 1);
            __syncthreads();
        }
    }

    // epilogue: c0/c1 at (fr, 2fc), c2/c3 at (fr+8, 2fc)
#pragma unroll
    for (int im = 0; im < 4; im++) {
#pragma unroll
        for (int in = 0; in < 4; in++) {
            long row = m0 + wm + im * 16 + fr;
            long col = n0 + wn + in * 8 + 2 * fc;
            *(float2*)(C + row * N + col)       = make_float2(acc[im][in][0], acc[im][in][1]);
            *(float2*)(C + (row + 8) * N + col) = make_float2(acc[im][in][2], acc[im][in][3]);
        }
    }
}

// ---------------------------------------------------------------------------
__global__ __launch_bounds__(256, 2) void qkv_kernel(
    const float* __restrict__ x,
    const float* __restrict__ Wq,
    const float* __restrict__ Wk,
    const float* __restrict__ Wv)
{
    const float* W = (blockIdx.z == 0) ? Wq : (blockIdx.z == 1) ? Wk : Wv;
    float* C       = (blockIdx.z == 0) ? g_Q : (blockIdx.z == 1) ? g_K : g_V;
    gemm_tf32_body<true>(x, W, C, DM, DM);
}

__global__ __launch_bounds__(256, 2) void scores_kernel()
{
    const long b = blockIdx.z;
    gemm_tf32_body<true>(g_Q + b * (long)SEQ * DM,
                         g_K + b * (long)SEQ * DM,
                         g_P + b * (long)SEQ * SEQ, SEQ, DM);
}

__global__ __launch_bounds__(256) void softmax_kernel()
{
    const long row = blockIdx.x;
    float* p = g_P + row * (long)SEQ;
    const int t = threadIdx.x;
    const float scale = 0.03125f;  // 1/sqrt(1024)

    float4 v0 = ((const float4*)p)[t];
    float4 v1 = ((const float4*)p)[t + 256];

    float m = fmaxf(fmaxf(fmaxf(v0.x, v0.y), fmaxf(v0.z, v0.w)),
                    fmaxf(fmaxf(v1.x, v1.y), fmaxf(v1.z, v1.w)));
    m *= scale;

    __shared__ float red[256];
    red[t] = m; __syncthreads();
#pragma unroll
    for (int s = 128; s > 0; s >>= 1) {
        if (t < s) red[t] = fmaxf(red[t], red[t + s]);
        __syncthreads();
    }
    const float rowmax = red[0];
    __syncthreads();

    float e[8];
    e[0] = __expf(fmaf(v0.x, scale, -rowmax));
    e[1] = __expf(fmaf(v0.y, scale, -rowmax));
    e[2] = __expf(fmaf(v0.z, scale, -rowmax));
    e[3] = __expf(fmaf(v0.w, scale, -rowmax));
    e[4] = __expf(fmaf(v1.x, scale, -rowmax));
    e[5] = __expf(fmaf(v1.y, scale, -rowmax));
    e[6] = __expf(fmaf(v1.z, scale, -rowmax));
    e[7] = __expf(fmaf(v1.w, scale, -rowmax));

    float s8 = e[0]+e[1]+e[2]+e[3]+e[4]+e[5]+e[6]+e[7];
    red[t] = s8; __syncthreads();
#pragma unroll
    for (int s = 128; s > 0; s >>= 1) {
        if (t < s) red[t] += red[t + s];
        __syncthreads();
    }
    const float inv = 1.0f / red[0];

    ((float4*)p)[t]       = make_float4(e[0]*inv, e[1]*inv, e[2]*inv, e[3]*inv);
    ((float4*)p)[t + 256] = make_float4(e[4]*inv, e[5]*inv, e[6]*inv, e[7]*inv);
}

__global__ __launch_bounds__(256, 2) void out_kernel(float* __restrict__ out)
{
    const long b = blockIdx.z;
    gemm_tf32_body<false>(g_P + b * (long)SEQ * SEQ,
                          g_V + b * (long)SEQ * DM,
                          out + b * (long)SEQ * DM, DM, SEQ);
}

// ---------------------------------------------------------------------------
extern "C" void kernel_launch(void* const* d_in, const int* in_sizes, int n_in,
                              void* d_out, int out_size)
{
    const float* x  = (const float*)d_in[0];
    const float* Wq = (const float*)d_in[1];
    const float* Wk = (const float*)d_in[2];
    const float* Wv = (const float*)d_in[3];
    float* out = (float*)d_out;

    dim3 blk(256);
    qkv_kernel   <<<dim3(DM / BN,  MTOT / BM, 3),     blk>>>(x, Wq, Wk, Wv);
    scores_kernel<<<dim3(SEQ / BN, SEQ / BM,  BATCH), blk>>>();
    softmax_kernel<<<BATCH * SEQ, 256>>>();
    out_kernel   <<<dim3(DM / BN,  SEQ / BM,  BATCH), blk>>>(out);
}

// round 6
// speedup vs baseline: 2.3577x; 1.1570x over previous
#include <cuda_runtime.h>
#include <cstdint>

// Shape: x [B=4, S=2048, D=1024] fp32; Wq/Wk/Wv [D, D] fp32 (y = x @ W^T)
#define BATCH 4
#define SEQ   2048
#define DM    1024
#define MTOT  (BATCH * SEQ)   // 8192

__device__ float g_Q[MTOT * DM];
__device__ float g_K[MTOT * DM];
__device__ float g_V[MTOT * DM];
__device__ float g_P[(long)MTOT * SEQ];

// ---------------------------------------------------------------------------
// TF32 mma.sync GEMM, cp.async 3-stage pipeline, BK=32.
// Block tile 128x128, 256 threads = 8 warps (2x4), warp tile 64x32.
// A smem / B_NK smem: 128 rows x 128B, SW128 xor swizzle (chunk ^= row&7)
//   -> cp.async 16B stores and ldmatrix reads both conflict-free.
// B_KN smem: 32 k-rows x 136 words (odd stride) -> scalar LDS conflict-free,
//   cp.async 16B stores conflict-free.
// fp32->tf32 RN conversion applied on fragment registers after ldmatrix.
// ---------------------------------------------------------------------------
#define TBK 32
#define STAGES 3
#define A_STAGE 16384                 // 128 * 128B
#define BNK_STAGE 16384
#define BKN_STAGE 17408               // 32 * 136 * 4
#define DYN_NK (STAGES * (A_STAGE + BNK_STAGE) + 256)
#define DYN_KN (STAGES * (A_STAGE + BKN_STAGE) + 256)

__device__ __forceinline__ uint32_t smem_u32(const void* p) {
    uint32_t a;
    asm("{ .reg .u64 t; cvta.to.shared.u64 t, %1; cvt.u32.u64 %0, t; }" : "=r"(a) : "l"(p));
    return a;
}
__device__ __forceinline__ uint32_t f2tf32(float f) {
    uint32_t o; asm("cvt.rna.tf32.f32 %0, %1;" : "=r"(o) : "f"(f)); return o;
}
__device__ __forceinline__ uint32_t cvt_frag(uint32_t bits) {
    return f2tf32(__uint_as_float(bits));
}
__device__ __forceinline__ void mma_tf32(
    float c[4], uint32_t a0, uint32_t a1, uint32_t a2, uint32_t a3,
    uint32_t b0, uint32_t b1)
{
    asm volatile(
        "mma.sync.aligned.m16n8k8.row.col.f32.tf32.tf32.f32 "
        "{%0,%1,%2,%3}, {%4,%5,%6,%7}, {%8,%9}, {%0,%1,%2,%3};"
        : "+f"(c[0]), "+f"(c[1]), "+f"(c[2]), "+f"(c[3])
        : "r"(a0), "r"(a1), "r"(a2), "r"(a3), "r"(b0), "r"(b1));
}
__device__ __forceinline__ void ldsm_x4(
    uint32_t& r0, uint32_t& r1, uint32_t& r2, uint32_t& r3, uint32_t addr)
{
    asm volatile("ldmatrix.sync.aligned.m8n8.x4.shared.b16 {%0,%1,%2,%3}, [%4];"
                 : "=r"(r0), "=r"(r1), "=r"(r2), "=r"(r3) : "r"(addr));
}
__device__ __forceinline__ void cp16(uint32_t dst, const float* src) {
    asm volatile("cp.async.cg.shared.global [%0], [%1], 16;" :: "r"(dst), "l"(src));
}
#define CP_COMMIT() asm volatile("cp.async.commit_group;" ::: "memory")
#define CP_WAIT1()  asm volatile("cp.async.wait_group 1;" ::: "memory")

// B_NK = true : C[m][n] = sum_k A[m][k] * B[n][k]   (B row-major [N,K])
// B_NK = false: C[m][n] = sum_k A[m][k] * B[k][n]   (B row-major [K,N])
template <bool B_NK>
__device__ __forceinline__ void gemm_body(
    const float* __restrict__ A, long lda,
    const float* __restrict__ B, long ldb,
    float* __restrict__ C, long ldc, int K)
{
    constexpr int BSTAGE = B_NK ? BNK_STAGE : BKN_STAGE;
    constexpr int STAGE  = A_STAGE + BSTAGE;
    extern __shared__ char dynsm[];
    const uint32_t sraw = smem_u32(dynsm);
    const uint32_t sb   = (sraw + 127) & ~127u;
    const uint32_t* dynw = (const uint32_t*)(dynsm + (sb - sraw));  // generic view

    const int t = threadIdx.x, lane = t & 31, warp = t >> 5;
    const int m0 = blockIdx.y * 128, n0 = blockIdx.x * 128;
    const int wm = (warp >> 2) * 64, wn = (warp & 3) * 32;
    const int fr = lane >> 2, fc = lane & 3;

    auto load_stage = [&](int slot, int k0) {
        const uint32_t ab = sb + slot * STAGE;
        const uint32_t bb = ab + A_STAGE;
#pragma unroll
        for (int it = 0; it < 4; it++) {
            int idx = t + it * 256;
            int row = idx >> 3, c16 = idx & 7;
            cp16(ab + row * 128 + ((c16 ^ (row & 7)) << 4),
                 A + (long)(m0 + row) * lda + k0 + c16 * 4);
        }
        if (B_NK) {
#pragma unroll
            for (int it = 0; it < 4; it++) {
                int idx = t + it * 256;
                int row = idx >> 3, c16 = idx & 7;
                cp16(bb + row * 128 + ((c16 ^ (row & 7)) << 4),
                     B + (long)(n0 + row) * ldb + k0 + c16 * 4);
            }
        } else {
#pragma unroll
            for (int it = 0; it < 4; it++) {
                int idx = t + it * 256;
                int k = idx >> 5, c16 = idx & 31;
                cp16(bb + k * 544 + c16 * 16,
                     B + (long)(k0 + k) * ldb + n0 + c16 * 4);
            }
        }
    };

    float acc[4][4][4];
#pragma unroll
    for (int i = 0; i < 4; i++)
#pragma unroll
        for (int j = 0; j < 4; j++)
#pragma unroll
            for (int r = 0; r < 4; r++) acc[i][j][r] = 0.f;

    // ldmatrix lane addressing (row&7 == lane&7 for all our rows)
    const int x7    = lane & 7;
    const int a_row = wm + ((lane >> 3) & 1) * 8 + x7;
    const int a_kc  = (lane >> 4) & 1;
    const int b_row = wn + ((lane >> 4) & 1) * 8 + x7;
    const int b_kc  = (lane >> 3) & 1;

    const int nT = K / TBK;
    load_stage(0, 0);   CP_COMMIT();
    load_stage(1, TBK); CP_COMMIT();

    for (int ti = 0; ti < nT; ti++) {
        CP_WAIT1();
        __syncthreads();

        const int pf = ti + 2;
        if (pf < nT) load_stage(pf % STAGES, pf * TBK);
        CP_COMMIT();

        const int slot = ti % STAGES;
        const uint32_t ab = sb + slot * STAGE;
        const uint32_t bb = ab + A_STAGE;
        const uint32_t* bw = dynw + (slot * STAGE + A_STAGE) / 4;

#pragma unroll
        for (int ks = 0; ks < 4; ks++) {
            const int kbc = ks * 2;
            uint32_t af[4][4], bf[4][2];
#pragma unroll
            for (int im = 0; im < 4; im++) {
                uint32_t addr = ab + (a_row + im * 16) * 128 + (((kbc + a_kc) ^ x7) << 4);
                ldsm_x4(af[im][0], af[im][1], af[im][2], af[im][3], addr);
            }
            if (B_NK) {
#pragma unroll
                for (int p = 0; p < 2; p++) {
                    uint32_t addr = bb + (b_row + p * 16) * 128 + (((kbc + b_kc) ^ x7) << 4);
                    ldsm_x4(bf[2 * p][0], bf[2 * p][1],
                            bf[2 * p + 1][0], bf[2 * p + 1][1], addr);
                }
            } else {
                const int kb = ks * 8;
#pragma unroll
                for (int in = 0; in < 4; in++) {
                    bf[in][0] = bw[(kb + fc) * 136 + wn + in * 8 + fr];
                    bf[in][1] = bw[(kb + fc + 4) * 136 + wn + in * 8 + fr];
                }
            }
#pragma unroll
            for (int im = 0; im < 4; im++)
#pragma unroll
                for (int j = 0; j < 4; j++) af[im][j] = cvt_frag(af[im][j]);
#pragma unroll
            for (int in = 0; in < 4; in++) {
                bf[in][0] = cvt_frag(bf[in][0]);
                bf[in][1] = cvt_frag(bf[in][1]);
            }
#pragma unroll
            for (int im = 0; im < 4; im++)
#pragma unroll
                for (int in = 0; in < 4; in++)
                    mma_tf32(acc[im][in], af[im][0], af[im][1], af[im][2], af[im][3],
                             bf[in][0], bf[in][1]);
        }
    }

    // epilogue: c0/c1 at (fr, 2fc), c2/c3 at (fr+8, 2fc)
#pragma unroll
    for (int im = 0; im < 4; im++) {
#pragma unroll
        for (int in = 0; in < 4; in++) {
            long row = m0 + wm + im * 16 + fr;
            long col = n0 + wn + in * 8 + 2 * fc;
            *(float2*)(C + row * ldc + col)       = make_float2(acc[im][in][0], acc[im][in][1]);
            *(float2*)(C + (row + 8) * ldc + col) = make_float2(acc[im][in][2], acc[im][in][3]);
        }
    }
}

// ---------------------------------------------------------------------------
__global__ __launch_bounds__(256, 2) void qkv_kernel(
    const float* __restrict__ x,
    const float* __restrict__ Wq,
    const float* __restrict__ Wk,
    const float* __restrict__ Wv)
{
    const float* W = (blockIdx.z == 0) ? Wq : (blockIdx.z == 1) ? Wk : Wv;
    float* C       = (blockIdx.z == 0) ? g_Q : (blockIdx.z == 1) ? g_K : g_V;
    gemm_body<true>(x, DM, W, DM, C, DM, DM);
}

__global__ __launch_bounds__(256, 2) void scores_kernel()
{
    const long b = blockIdx.z;
    gemm_body<true>(g_Q + b * (long)SEQ * DM, DM,
                    g_K + b * (long)SEQ * DM, DM,
                    g_P + b * (long)SEQ * SEQ, SEQ, DM);
}

__global__ __launch_bounds__(256, 2) void out_kernel(float* __restrict__ out)
{
    const long b = blockIdx.z;
    gemm_body<false>(g_P + b * (long)SEQ * SEQ, SEQ,
                     g_V + b * (long)SEQ * DM, DM,
                     out + b * (long)SEQ * DM, DM, SEQ);
}

__global__ __launch_bounds__(256) void softmax_kernel()
{
    const long row = blockIdx.x;
    float* p = g_P + row * (long)SEQ;
    const int t = threadIdx.x;
    const float scale = 0.03125f;  // 1/sqrt(1024)

    float4 v0 = ((const float4*)p)[t];
    float4 v1 = ((const float4*)p)[t + 256];

    float m = fmaxf(fmaxf(fmaxf(v0.x, v0.y), fmaxf(v0.z, v0.w)),
                    fmaxf(fmaxf(v1.x, v1.y), fmaxf(v1.z, v1.w)));
    m *= scale;

    __shared__ float red[256];
    red[t] = m; __syncthreads();
#pragma unroll
    for (int s = 128; s > 0; s >>= 1) {
        if (t < s) red[t] = fmaxf(red[t], red[t + s]);
        __syncthreads();
    }
    const float rowmax = red[0];
    __syncthreads();

    float e[8];
    e[0] = __expf(fmaf(v0.x, scale, -rowmax));
    e[1] = __expf(fmaf(v0.y, scale, -rowmax));
    e[2] = __expf(fmaf(v0.z, scale, -rowmax));
    e[3] = __expf(fmaf(v0.w, scale, -rowmax));
    e[4] = __expf(fmaf(v1.x, scale, -rowmax));
    e[5] = __expf(fmaf(v1.y, scale, -rowmax));
    e[6] = __expf(fmaf(v1.z, scale, -rowmax));
    e[7] = __expf(fmaf(v1.w, scale, -rowmax));

    float s8 = e[0]+e[1]+e[2]+e[3]+e[4]+e[5]+e[6]+e[7];
    red[t] = s8; __syncthreads();
#pragma unroll
    for (int s = 128; s > 0; s >>= 1) {
        if (t < s) red[t] += red[t + s];
        __syncthreads();
    }
    const float inv = 1.0f / red[0];

    ((float4*)p)[t]       = make_float4(e[0]*inv, e[1]*inv, e[2]*inv, e[3]*inv);
    ((float4*)p)[t + 256] = make_float4(e[4]*inv, e[5]*inv, e[6]*inv, e[7]*inv);
}

// ---------------------------------------------------------------------------
extern "C" void kernel_launch(void* const* d_in, const int* in_sizes, int n_in,
                              void* d_out, int out_size)
{
    const float* x  = (const float*)d_in[0];
    const float* Wq = (const float*)d_in[1];
    const float* Wk = (const float*)d_in[2];
    const float* Wv = (const float*)d_in[3];
    float* out = (float*)d_out;

    static bool attr_done = false;
    if (!attr_done) {
        cudaFuncSetAttribute(qkv_kernel,    cudaFuncAttributeMaxDynamicSharedMemorySize, DYN_NK);
        cudaFuncSetAttribute(scores_kernel, cudaFuncAttributeMaxDynamicSharedMemorySize, DYN_NK);
        cudaFuncSetAttribute(out_kernel,    cudaFuncAttributeMaxDynamicSharedMemorySize, DYN_KN);
        attr_done = true;
    }

    dim3 blk(256);
    qkv_kernel   <<<dim3(DM / 128,  MTOT / 128, 3),     blk, DYN_NK>>>(x, Wq, Wk, Wv);
    scores_kernel<<<dim3(SEQ / 128, SEQ / 128,  BATCH), blk, DYN_NK>>>();
    softmax_kernel<<<MTOT, 256>>>();
    out_kernel   <<<dim3(DM / 128,  SEQ / 128,  BATCH), blk, DYN_KN>>>(out);
}

// round 7
// speedup vs baseline: 2.7305x; 1.1581x over previous
#include <cuda_runtime.h>
#include <cstdint>

// Shape: x [B=4, S=2048, D=1024] fp32; Wq/Wk/Wv [D, D] fp32 (y = x @ W^T)
#define BATCH 4
#define SEQ   2048
#define DM    1024
#define MTOT  (BATCH * SEQ)   // 8192

__device__ float g_X[MTOT * DM];          // tf32-rounded x
__device__ float g_W[3 * DM * DM];        // tf32-rounded Wq|Wk|Wv
__device__ float g_Q[MTOT * DM];
__device__ float g_K[MTOT * DM];
__device__ float g_V[MTOT * DM];
__device__ float g_P[(long)MTOT * SEQ];

// ---------------------------------------------------------------------------
// TF32 mma.sync GEMM, cp.async 3-stage pipeline, BK=32. All operands arrive
// pre-rounded to tf32 (RNA), so the mainloop has NO cvt instructions.
// Block tile 128x128, 256 threads = 8 warps (2x4), warp tile 64x32.
// ---------------------------------------------------------------------------
#define TBK 32
#define STAGES 3
#define A_STAGE 16384
#define BNK_STAGE 16384
#define BKN_STAGE 17408               // 32 * 136 * 4
#define DYN_NK (STAGES * (A_STAGE + BNK_STAGE) + 256)
#define DYN_KN (STAGES * (A_STAGE + BKN_STAGE) + 256)

__device__ __forceinline__ uint32_t smem_u32(const void* p) {
    uint32_t a;
    asm("{ .reg .u64 t; cvta.to.shared.u64 t, %1; cvt.u32.u64 %0, t; }" : "=r"(a) : "l"(p));
    return a;
}
__device__ __forceinline__ float tf32r(float f) {
    uint32_t o; asm("cvt.rna.tf32.f32 %0, %1;" : "=r"(o) : "f"(f));
    return __uint_as_float(o);
}
__device__ __forceinline__ void mma_tf32(
    float c[4], uint32_t a0, uint32_t a1, uint32_t a2, uint32_t a3,
    uint32_t b0, uint32_t b1)
{
    asm volatile(
        "mma.sync.aligned.m16n8k8.row.col.f32.tf32.tf32.f32 "
        "{%0,%1,%2,%3}, {%4,%5,%6,%7}, {%8,%9}, {%0,%1,%2,%3};"
        : "+f"(c[0]), "+f"(c[1]), "+f"(c[2]), "+f"(c[3])
        : "r"(a0), "r"(a1), "r"(a2), "r"(a3), "r"(b0), "r"(b1));
}
__device__ __forceinline__ void ldsm_x4(
    uint32_t& r0, uint32_t& r1, uint32_t& r2, uint32_t& r3, uint32_t addr)
{
    asm volatile("ldmatrix.sync.aligned.m8n8.x4.shared.b16 {%0,%1,%2,%3}, [%4];"
                 : "=r"(r0), "=r"(r1), "=r"(r2), "=r"(r3) : "r"(addr));
}
__device__ __forceinline__ void cp16(uint32_t dst, const float* src) {
    asm volatile("cp.async.cg.shared.global [%0], [%1], 16;" :: "r"(dst), "l"(src));
}
#define CP_COMMIT() asm volatile("cp.async.commit_group;" ::: "memory")
#define CP_WAIT1()  asm volatile("cp.async.wait_group 1;" ::: "memory")

// B_NK = true : C[m][n] = sum_k A[m][k] * B[n][k]
// B_NK = false: C[m][n] = sum_k A[m][k] * B[k][n]
// ROUND_C: round outputs to tf32 (RNA) before the store.
template <bool B_NK, bool ROUND_C>
__device__ __forceinline__ void gemm_body(
    const float* __restrict__ A, long lda,
    const float* __restrict__ B, long ldb,
    float* __restrict__ C, long ldc, int K)
{
    constexpr int BSTAGE = B_NK ? BNK_STAGE : BKN_STAGE;
    constexpr int STAGE  = A_STAGE + BSTAGE;
    extern __shared__ char dynsm[];
    const uint32_t sraw = smem_u32(dynsm);
    const uint32_t sb   = (sraw + 127) & ~127u;
    const uint32_t* dynw = (const uint32_t*)(dynsm + (sb - sraw));

    const int t = threadIdx.x, lane = t & 31, warp = t >> 5;
    const int m0 = blockIdx.y * 128, n0 = blockIdx.x * 128;
    const int wm = (warp >> 2) * 64, wn = (warp & 3) * 32;
    const int fr = lane >> 2, fc = lane & 3;

    auto load_stage = [&](int slot, int k0) {
        const uint32_t ab = sb + slot * STAGE;
        const uint32_t bb = ab + A_STAGE;
#pragma unroll
        for (int it = 0; it < 4; it++) {
            int idx = t + it * 256;
            int row = idx >> 3, c16 = idx & 7;
            cp16(ab + row * 128 + ((c16 ^ (row & 7)) << 4),
                 A + (long)(m0 + row) * lda + k0 + c16 * 4);
        }
        if (B_NK) {
#pragma unroll
            for (int it = 0; it < 4; it++) {
                int idx = t + it * 256;
                int row = idx >> 3, c16 = idx & 7;
                cp16(bb + row * 128 + ((c16 ^ (row & 7)) << 4),
                     B + (long)(n0 + row) * ldb + k0 + c16 * 4);
            }
        } else {
#pragma unroll
            for (int it = 0; it < 4; it++) {
                int idx = t + it * 256;
                int k = idx >> 5, c16 = idx & 31;
                cp16(bb + k * 544 + c16 * 16,
                     B + (long)(k0 + k) * ldb + n0 + c16 * 4);
            }
        }
    };

    float acc[4][4][4];
#pragma unroll
    for (int i = 0; i < 4; i++)
#pragma unroll
        for (int j = 0; j < 4; j++)
#pragma unroll
            for (int r = 0; r < 4; r++) acc[i][j][r] = 0.f;

    const int x7    = lane & 7;
    const int a_row = wm + ((lane >> 3) & 1) * 8 + x7;
    const int a_kc  = (lane >> 4) & 1;
    const int b_row = wn + ((lane >> 4) & 1) * 8 + x7;
    const int b_kc  = (lane >> 3) & 1;

    const int nT = K / TBK;
    load_stage(0, 0);   CP_COMMIT();
    load_stage(1, TBK); CP_COMMIT();

    for (int ti = 0; ti < nT; ti++) {
        CP_WAIT1();
        __syncthreads();

        const int pf = ti + 2;
        if (pf < nT) load_stage(pf % STAGES, pf * TBK);
        CP_COMMIT();

        const int slot = ti % STAGES;
        const uint32_t ab = sb + slot * STAGE;
        const uint32_t bb = ab + A_STAGE;
        const uint32_t* bw = dynw + (slot * STAGE + A_STAGE) / 4;

#pragma unroll
        for (int ks = 0; ks < 4; ks++) {
            const int kbc = ks * 2;
            uint32_t af[4][4], bf[4][2];
#pragma unroll
            for (int im = 0; im < 4; im++) {
                uint32_t addr = ab + (a_row + im * 16) * 128 + (((kbc + a_kc) ^ x7) << 4);
                ldsm_x4(af[im][0], af[im][1], af[im][2], af[im][3], addr);
            }
            if (B_NK) {
#pragma unroll
                for (int p = 0; p < 2; p++) {
                    uint32_t addr = bb + (b_row + p * 16) * 128 + (((kbc + b_kc) ^ x7) << 4);
                    ldsm_x4(bf[2 * p][0], bf[2 * p][1],
                            bf[2 * p + 1][0], bf[2 * p + 1][1], addr);
                }
            } else {
                const int kb = ks * 8;
#pragma unroll
                for (int in = 0; in < 4; in++) {
                    bf[in][0] = bw[(kb + fc) * 136 + wn + in * 8 + fr];
                    bf[in][1] = bw[(kb + fc + 4) * 136 + wn + in * 8 + fr];
                }
            }
#pragma unroll
            for (int im = 0; im < 4; im++)
#pragma unroll
                for (int in = 0; in < 4; in++)
                    mma_tf32(acc[im][in], af[im][0], af[im][1], af[im][2], af[im][3],
                             bf[in][0], bf[in][1]);
        }
    }

#pragma unroll
    for (int im = 0; im < 4; im++) {
#pragma unroll
        for (int in = 0; in < 4; in++) {
            float v0 = acc[im][in][0], v1 = acc[im][in][1];
            float v2 = acc[im][in][2], v3 = acc[im][in][3];
            if (ROUND_C) { v0 = tf32r(v0); v1 = tf32r(v1); v2 = tf32r(v2); v3 = tf32r(v3); }
            long row = m0 + wm + im * 16 + fr;
            long col = n0 + wn + in * 8 + 2 * fc;
            *(float2*)(C + row * ldc + col)       = make_float2(v0, v1);
            *(float2*)(C + (row + 8) * ldc + col) = make_float2(v2, v3);
        }
    }
}

// ---------------------------------------------------------------------------
__global__ __launch_bounds__(256) void round_kernel(
    const float* __restrict__ src, float* __restrict__ dst)
{
    const long i = (long)(blockIdx.x * 256 + threadIdx.x) * 4;
    float4 v = *(const float4*)(src + i);
    *(float4*)(dst + i) = make_float4(tf32r(v.x), tf32r(v.y), tf32r(v.z), tf32r(v.w));
}

__global__ __launch_bounds__(256, 2) void qkv_kernel()
{
    const float* W = g_W + (long)blockIdx.z * DM * DM;
    float* C = (blockIdx.z == 0) ? g_Q : (blockIdx.z == 1) ? g_K : g_V;
    gemm_body<true, true>(g_X, DM, W, DM, C, DM, DM);
}

__global__ __launch_bounds__(256, 2) void scores_kernel()
{
    const long b = blockIdx.z;
    gemm_body<true, false>(g_Q + b * (long)SEQ * DM, DM,
                           g_K + b * (long)SEQ * DM, DM,
                           g_P + b * (long)SEQ * SEQ, SEQ, DM);
}

__global__ __launch_bounds__(256, 2) void out_kernel(float* __restrict__ out)
{
    const long b = blockIdx.z;
    gemm_body<false, false>(g_P + b * (long)SEQ * SEQ, SEQ,
                            g_V + b * (long)SEQ * DM, DM,
                            out + b * (long)SEQ * DM, DM, SEQ);
}

__global__ __launch_bounds__(256) void softmax_kernel()
{
    const long row = blockIdx.x;
    float* p = g_P + row * (long)SEQ;
    const int t = threadIdx.x;
    const float scale = 0.03125f;  // 1/sqrt(1024)

    float4 v0 = ((const float4*)p)[t];
    float4 v1 = ((const float4*)p)[t + 256];

    float m = fmaxf(fmaxf(fmaxf(v0.x, v0.y), fmaxf(v0.z, v0.w)),
                    fmaxf(fmaxf(v1.x, v1.y), fmaxf(v1.z, v1.w)));
    m *= scale;

    __shared__ float red[256];
    red[t] = m; __syncthreads();
#pragma unroll
    for (int s = 128; s > 0; s >>= 1) {
        if (t < s) red[t] = fmaxf(red[t], red[t + s]);
        __syncthreads();
    }
    const float rowmax = red[0];
    __syncthreads();

    float e[8];
    e[0] = __expf(fmaf(v0.x, scale, -rowmax));
    e[1] = __expf(fmaf(v0.y, scale, -rowmax));
    e[2] = __expf(fmaf(v0.z, scale, -rowmax));
    e[3] = __expf(fmaf(v0.w, scale, -rowmax));
    e[4] = __expf(fmaf(v1.x, scale, -rowmax));
    e[5] = __expf(fmaf(v1.y, scale, -rowmax));
    e[6] = __expf(fmaf(v1.z, scale, -rowmax));
    e[7] = __expf(fmaf(v1.w, scale, -rowmax));

    float s8 = e[0]+e[1]+e[2]+e[3]+e[4]+e[5]+e[6]+e[7];
    red[t] = s8; __syncthreads();
#pragma unroll
    for (int s = 128; s > 0; s >>= 1) {
        if (t < s) red[t] += red[t + s];
        __syncthreads();
    }
    const float inv = 1.0f / red[0];

    // write probs pre-rounded to tf32 (RNA) for the out GEMM
    ((float4*)p)[t] = make_float4(tf32r(e[0]*inv), tf32r(e[1]*inv),
                                  tf32r(e[2]*inv), tf32r(e[3]*inv));
    ((float4*)p)[t + 256] = make_float4(tf32r(e[4]*inv), tf32r(e[5]*inv),
                                        tf32r(e[6]*inv), tf32r(e[7]*inv));
}

// ---------------------------------------------------------------------------
extern "C" void kernel_launch(void* const* d_in, const int* in_sizes, int n_in,
                              void* d_out, int out_size)
{
    const float* x  = (const float*)d_in[0];
    const float* Wq = (const float*)d_in[1];
    const float* Wk = (const float*)d_in[2];
    const float* Wv = (const float*)d_in[3];
    float* out = (float*)d_out;

    static bool attr_done = false;
    if (!attr_done) {
        cudaFuncSetAttribute(qkv_kernel,    cudaFuncAttributeMaxDynamicSharedMemorySize, DYN_NK);
        cudaFuncSetAttribute(scores_kernel, cudaFuncAttributeMaxDynamicSharedMemorySize, DYN_NK);
        cudaFuncSetAttribute(out_kernel,    cudaFuncAttributeMaxDynamicSharedMemorySize, DYN_KN);
        attr_done = true;
    }

    float* gX; cudaGetSymbolAddress((void**)&gX, g_X);
    float* gW; cudaGetSymbolAddress((void**)&gW, g_W);

    dim3 blk(256);
    round_kernel<<<MTOT * DM / 1024, blk>>>(x, gX);
    round_kernel<<<DM * DM / 1024, blk>>>(Wq, gW);
    round_kernel<<<DM * DM / 1024, blk>>>(Wk, gW + (long)DM * DM);
    round_kernel<<<DM * DM / 1024, blk>>>(Wv, gW + 2L * DM * DM);

    qkv_kernel   <<<dim3(DM / 128,  MTOT / 128, 3),     blk, DYN_NK>>>();
    scores_kernel<<<dim3(SEQ / 128, SEQ / 128,  BATCH), blk, DYN_NK>>>();
    softmax_kernel<<<MTOT, 256>>>();
    out_kernel   <<<dim3(DM / 128,  SEQ / 128,  BATCH), blk, DYN_KN>>>(out);
}